// round 8
// baseline (speedup 1.0000x reference)
#include <cuda_runtime.h>
#include <cstdint>

// CenterLoss: loss = (1/B) * sum_b clamp(|x_b - c_{l_b}|^2, 1e-12, 1e12) + (C-1)*1e-12
// (|x|^2+|c|^2-2xc == sum (x-c)^2; one-hot mask keeps only the true-label column,
//  masked-out zeros clamp to 1e-12 each.)
//
// Single fused kernel. Finalize via HIERARCHICAL last-done counters:
// 2048 blocks -> 32 level-1 counters (64 blocks each) -> 1 level-2 counter.
// Max same-address atomic contention is 64, not 2048 (R4/R5 lost ~5us to a
// single hot counter). Increments are atom.release.gpu; bucket sums are L2
// atomics, so the release chain makes them visible to the finalizer.

#define B_ROWS 16384
#define C_CLASSES 1000
#define D_DIM 512
#define WARPS_PER_BLOCK 8
#define THREADS (WARPS_PER_BLOCK * 32)
#define GRID_BLOCKS (B_ROWS / WARPS_PER_BLOCK)   // 2048
#define N_GROUPS 32
#define BLOCKS_PER_GROUP (GRID_BLOCKS / N_GROUPS) // 64

__device__ double g_buckets[N_GROUPS];            // zero-init at load
__device__ unsigned int g_done1[N_GROUPS];        // zero-init at load
__device__ unsigned int g_done2 = 0;

__device__ __forceinline__ unsigned int release_inc(unsigned int* p) {
    unsigned int prev;
    asm volatile("atom.release.gpu.global.add.u32 %0, [%1], %2;"
                 : "=r"(prev) : "l"(p), "r"(1u) : "memory");
    return prev;
}

__global__ __launch_bounds__(THREADS) void center_loss_fused(
    const float* __restrict__ x,
    const int* __restrict__ labels,
    const float* __restrict__ centers,
    float* __restrict__ out)
{
    __shared__ float warp_part[WARPS_PER_BLOCK];
    const int warp_in_block = threadIdx.x >> 5;
    const int lane = threadIdx.x & 31;
    const int row = blockIdx.x * WARPS_PER_BLOCK + warp_in_block;

    {
        int lbl = labels[row];
        lbl = (lbl < 0) ? 0 : ((lbl >= C_CLASSES) ? C_CLASSES - 1 : lbl);

        const float4* __restrict__ xr =
            reinterpret_cast<const float4*>(x + (size_t)row * D_DIM);
        const float4* __restrict__ cr =
            reinterpret_cast<const float4*>(centers + (size_t)lbl * D_DIM);

        // 512 floats / 32 lanes = 4 float4 per lane; loads front-batched.
        float4 xv[4], cv[4];
#pragma unroll
        for (int i = 0; i < 4; i++) xv[i] = xr[lane + 32 * i];
#pragma unroll
        for (int i = 0; i < 4; i++) cv[i] = cr[lane + 32 * i];

        float d = 0.f;
#pragma unroll
        for (int i = 0; i < 4; i++) {
            float t;
            t = xv[i].x - cv[i].x; d = fmaf(t, t, d);
            t = xv[i].y - cv[i].y; d = fmaf(t, t, d);
            t = xv[i].z - cv[i].z; d = fmaf(t, t, d);
            t = xv[i].w - cv[i].w; d = fmaf(t, t, d);
        }

        // single-value warp reduce (5 shuffles)
#pragma unroll
        for (int o = 16; o > 0; o >>= 1)
            d += __shfl_xor_sync(0xFFFFFFFFu, d, o);

        if (lane == 0) {
            d = fminf(fmaxf(d, 1e-12f), 1e12f);   // clamp per reference
            warp_part[warp_in_block] = d;
        }
    }
    __syncthreads();

    if (warp_in_block == 0) {
        float v = (lane < WARPS_PER_BLOCK) ? warp_part[lane] : 0.f;
#pragma unroll
        for (int o = 4; o > 0; o >>= 1)
            v += __shfl_xor_sync(0xFFFFFFFFu, v, o);

        if (lane == 0) {
            const int grp = blockIdx.x & (N_GROUPS - 1);
            atomicAdd(&g_buckets[grp], (double)v);

            // level-1: 64 blocks per counter
            unsigned int p1 = release_inc(&g_done1[grp]);
            if (p1 == BLOCKS_PER_GROUP - 1) {
                // level-2: 32 group-last blocks
                unsigned int p2 = release_inc(&g_done2);
                if (p2 == N_GROUPS - 1) {
                    // true last block: all bucket adds are L2-visible
                    double total = 0.0;
#pragma unroll
                    for (int i = 0; i < N_GROUPS; i++)
                        total += atomicAdd(&g_buckets[i], 0.0);  // L2 read
                    double loss = total / (double)B_ROWS
                                + (double)(C_CLASSES - 1) * 1e-12;
                    out[0] = (float)loss;
                    // reset for next graph replay
#pragma unroll
                    for (int i = 0; i < N_GROUPS; i++) {
                        g_buckets[i] = 0.0;
                        g_done1[i] = 0u;
                    }
                    g_done2 = 0u;
                }
            }
        }
    }
}

extern "C" void kernel_launch(void* const* d_in, const int* in_sizes, int n_in,
                              void* d_out, int out_size)
{
    const float* x = (const float*)d_in[0];
    const int* labels = (const int*)d_in[1];
    const float* centers = (const float*)d_in[2];
    float* out = (float*)d_out;

    center_loss_fused<<<GRID_BLOCKS, THREADS>>>(x, labels, centers, out);
}

// round 9
// speedup vs baseline: 1.5829x; 1.5829x over previous
#include <cuda_runtime.h>
#include <cstdint>

// CenterLoss: loss = (1/B) * sum_b clamp(|x_b - c_{l_b}|^2, 1e-12, 1e12) [+ (C-1)*1e-12]
// (identical to |x|^2+|c|^2-2xc with the one-hot mask; the masked-zero clamp
//  constant is 999e-12 against a loss of ~1e3 -> rel 1e-12, below fp32 eps, dropped.)
//
// Structure (reverted to the measured-fastest R3 shape, finalize deleted):
//   node 1: cudaMemsetAsync(out, 0, 4)   -- graph memset node, zeroes scalar per replay
//   node 2: rows kernel; each block does ONE no-return float atomicAdd(out, partial/B)
//           -> REDG (fire-and-forget), no last-block-done retirement coupling,
//              which cost ~5us in R4/R5/R6 in every flavor tried.

#define B_ROWS 16384
#define C_CLASSES 1000
#define D_DIM 512
#define WARPS_PER_BLOCK 8
#define THREADS (WARPS_PER_BLOCK * 32)
#define GRID_BLOCKS (B_ROWS / WARPS_PER_BLOCK)   // 2048

__global__ __launch_bounds__(THREADS) void center_loss_rows(
    const float* __restrict__ x,
    const int* __restrict__ labels,
    const float* __restrict__ centers,
    float* __restrict__ out)
{
    __shared__ float warp_part[WARPS_PER_BLOCK];
    const int warp_in_block = threadIdx.x >> 5;
    const int lane = threadIdx.x & 31;
    const int row = blockIdx.x * WARPS_PER_BLOCK + warp_in_block;

    {
        int lbl = labels[row];
        lbl = (lbl < 0) ? 0 : ((lbl >= C_CLASSES) ? C_CLASSES - 1 : lbl);

        const float4* __restrict__ xr =
            reinterpret_cast<const float4*>(x + (size_t)row * D_DIM);
        const float4* __restrict__ cr =
            reinterpret_cast<const float4*>(centers + (size_t)lbl * D_DIM);

        // 512 floats / 32 lanes = 4 float4 per lane; loads front-batched for MLP.
        float4 xv[4], cv[4];
#pragma unroll
        for (int i = 0; i < 4; i++) xv[i] = xr[lane + 32 * i];
#pragma unroll
        for (int i = 0; i < 4; i++) cv[i] = cr[lane + 32 * i];

        float d = 0.f;
#pragma unroll
        for (int i = 0; i < 4; i++) {
            float t;
            t = xv[i].x - cv[i].x; d = fmaf(t, t, d);
            t = xv[i].y - cv[i].y; d = fmaf(t, t, d);
            t = xv[i].z - cv[i].z; d = fmaf(t, t, d);
            t = xv[i].w - cv[i].w; d = fmaf(t, t, d);
        }

        // per-row warp reduce (5 shuffles)
#pragma unroll
        for (int o = 16; o > 0; o >>= 1)
            d += __shfl_xor_sync(0xFFFFFFFFu, d, o);

        if (lane == 0) {
            d = fminf(fmaxf(d, 1e-12f), 1e12f);   // clamp per reference
            warp_part[warp_in_block] = d;
        }
    }
    __syncthreads();

    // block reduce in warp 0, single fire-and-forget atomic per block
    if (warp_in_block == 0) {
        float v = (lane < WARPS_PER_BLOCK) ? warp_part[lane] : 0.f;
#pragma unroll
        for (int o = 4; o > 0; o >>= 1)
            v += __shfl_xor_sync(0xFFFFFFFFu, v, o);

        if (lane == 0) {
            // pre-scale by 1/B in double, emit one float REDG (no return value)
            float contrib = (float)((double)v / (double)B_ROWS);
            atomicAdd(out, contrib);
        }
    }
}

extern "C" void kernel_launch(void* const* d_in, const int* in_sizes, int n_in,
                              void* d_out, int out_size)
{
    const float* x = (const float*)d_in[0];
    const int* labels = (const int*)d_in[1];
    const float* centers = (const float*)d_in[2];
    float* out = (float*)d_out;

    cudaMemsetAsync(out, 0, sizeof(float));   // graph memset node: zero per replay
    center_loss_rows<<<GRID_BLOCKS, THREADS>>>(x, labels, centers, out);
}

// round 12
// speedup vs baseline: 1.6264x; 1.0275x over previous
#include <cuda_runtime.h>
#include <cstdint>

// CenterLoss: loss = (1/B) * sum_b clamp(|x_b - c_{l_b}|^2, 1e-12, 1e12)
// (== |x|^2+|c|^2-2xc under the one-hot mask; the 999e-12 masked-zero constant
//  is rel 1e-12 against loss ~1e3, below fp32 eps, dropped.)
//
// Structure: memset node zeroes the scalar; rows kernel does one no-return
// float atomicAdd (REDG) per block. TWO rows per warp — both labels load
// first, then all 16 float4 loads issue before any FMA, doubling per-warp
// memory-level parallelism (R9 was latency-bound: issue=16%, DRAM=40%).
// [Resubmit of R10 — prior round was a container infra failure.]

#define B_ROWS 16384
#define C_CLASSES 1000
#define D_DIM 512
#define WARPS_PER_BLOCK 8
#define ROWS_PER_WARP 2
#define THREADS (WARPS_PER_BLOCK * 32)
#define ROWS_PER_BLOCK (WARPS_PER_BLOCK * ROWS_PER_WARP)     // 16
#define GRID_BLOCKS (B_ROWS / ROWS_PER_BLOCK)                // 1024

__global__ __launch_bounds__(THREADS) void center_loss_rows(
    const float* __restrict__ x,
    const int* __restrict__ labels,
    const float* __restrict__ centers,
    float* __restrict__ out)
{
    __shared__ float warp_part[WARPS_PER_BLOCK];
    const int warp_in_block = threadIdx.x >> 5;
    const int lane = threadIdx.x & 31;
    const int row0 = (blockIdx.x * WARPS_PER_BLOCK + warp_in_block) * ROWS_PER_WARP;
    const int row1 = row0 + 1;

    float dsum;
    {
        // both labels first (same-address broadcast loads, independent)
        int l0 = labels[row0];
        int l1 = labels[row1];
        l0 = (l0 < 0) ? 0 : ((l0 >= C_CLASSES) ? C_CLASSES - 1 : l0);
        l1 = (l1 < 0) ? 0 : ((l1 >= C_CLASSES) ? C_CLASSES - 1 : l1);

        const float4* __restrict__ xr0 =
            reinterpret_cast<const float4*>(x + (size_t)row0 * D_DIM);
        const float4* __restrict__ xr1 =
            reinterpret_cast<const float4*>(x + (size_t)row1 * D_DIM);
        const float4* __restrict__ cr0 =
            reinterpret_cast<const float4*>(centers + (size_t)l0 * D_DIM);
        const float4* __restrict__ cr1 =
            reinterpret_cast<const float4*>(centers + (size_t)l1 * D_DIM);

        // 16 independent float4 loads per lane, all issued before use (MLP=16)
        float4 xa[4], xb[4], ca[4], cb[4];
#pragma unroll
        for (int i = 0; i < 4; i++) xa[i] = xr0[lane + 32 * i];
#pragma unroll
        for (int i = 0; i < 4; i++) xb[i] = xr1[lane + 32 * i];
#pragma unroll
        for (int i = 0; i < 4; i++) ca[i] = cr0[lane + 32 * i];
#pragma unroll
        for (int i = 0; i < 4; i++) cb[i] = cr1[lane + 32 * i];

        float d0 = 0.f, d1 = 0.f;
#pragma unroll
        for (int i = 0; i < 4; i++) {
            float t;
            t = xa[i].x - ca[i].x; d0 = fmaf(t, t, d0);
            t = xa[i].y - ca[i].y; d0 = fmaf(t, t, d0);
            t = xa[i].z - ca[i].z; d0 = fmaf(t, t, d0);
            t = xa[i].w - ca[i].w; d0 = fmaf(t, t, d0);
            t = xb[i].x - cb[i].x; d1 = fmaf(t, t, d1);
            t = xb[i].y - cb[i].y; d1 = fmaf(t, t, d1);
            t = xb[i].z - cb[i].z; d1 = fmaf(t, t, d1);
            t = xb[i].w - cb[i].w; d1 = fmaf(t, t, d1);
        }

        // reduce both rows (clamp is per-row, before summing!)
#pragma unroll
        for (int o = 16; o > 0; o >>= 1) {
            d0 += __shfl_xor_sync(0xFFFFFFFFu, d0, o);
            d1 += __shfl_xor_sync(0xFFFFFFFFu, d1, o);
        }
        d0 = fminf(fmaxf(d0, 1e-12f), 1e12f);
        d1 = fminf(fmaxf(d1, 1e-12f), 1e12f);
        dsum = d0 + d1;

        if (lane == 0) warp_part[warp_in_block] = dsum;
    }
    __syncthreads();

    // block reduce in warp 0, single fire-and-forget atomic per block
    if (warp_in_block == 0) {
        float v = (lane < WARPS_PER_BLOCK) ? warp_part[lane] : 0.f;
#pragma unroll
        for (int o = 4; o > 0; o >>= 1)
            v += __shfl_xor_sync(0xFFFFFFFFu, v, o);

        if (lane == 0) {
            float contrib = (float)((double)v / (double)B_ROWS);
            atomicAdd(out, contrib);   // no-return -> REDG
        }
    }
}

extern "C" void kernel_launch(void* const* d_in, const int* in_sizes, int n_in,
                              void* d_out, int out_size)
{
    const float* x = (const float*)d_in[0];
    const int* labels = (const int*)d_in[1];
    const float* centers = (const float*)d_in[2];
    float* out = (float*)d_out;

    cudaMemsetAsync(out, 0, sizeof(float));   // graph memset node
    center_loss_rows<<<GRID_BLOCKS, THREADS>>>(x, labels, centers, out);
}